// round 1
// baseline (speedup 1.0000x reference)
#include <cuda_runtime.h>

#define BB 8
#define HH 512
#define WW 512
#define NMASK 2
#define BIGF 1.0e6f
#define BIG2 1.0e12f
#define NPIX (BB * HH * WW)          // 2097152 = 2^21

// Scratch: dt_sq for both masks ([mask][b][h][w]), per-(mask,batch) max bits, sum.
__device__ float        g_dtsq[NMASK * NPIX];     // 16 MB static scratch
__device__ unsigned int g_maxbits[NMASK * BB];
__device__ double       g_accum;

__global__ void k_init() {
    if (threadIdx.x < NMASK * BB) g_maxbits[threadIdx.x] = 0u;
    if (threadIdx.x == 0) g_accum = 0.0;
}

__device__ __forceinline__ bool is_fg(const float* __restrict__ out,
                                      const int* __restrict__ tgt,
                                      int m, int b, int h, int w) {
    if (m == 0) return tgt[(b * HH + h) * WW + w] > 0;                 // gt mask
    return out[((b * 2 + 1) * HH + h) * WW + w] > 0.5f;                // seg mask
}

// Pass 1: vertical 1D distance (exact match of the BIG-initialized fw/bw scans),
// adaptive radius search. Writes g^2.
__global__ void k_vert(const float* __restrict__ out, const int* __restrict__ tgt) {
    int idx = blockIdx.x * blockDim.x + threadIdx.x;   // [m][b][h][w], w fastest
    int w = idx & (WW - 1);
    int h = (idx >> 9) & (HH - 1);
    int b = (idx >> 18) & (BB - 1);
    int m = idx >> 21;

    float g;
    if (!is_fg(out, tgt, m, b, h, w)) {
        g = 0.0f;
    } else {
        int r = 1, found = 0;
        while (true) {
            bool up = (h - r >= 0);
            bool dn = (h + r < HH);
            if (!up && !dn) break;
            if (up && !is_fg(out, tgt, m, b, h - r, w)) { found = 1; break; }
            if (dn && !is_fg(out, tgt, m, b, h + r, w)) { found = 1; break; }
            ++r;
        }
        g = found ? (float)r : (BIGF + (float)min(h + 1, HH - h));
    }
    g_dtsq[idx] = g * g;
}

// Pass 2: per-row lower-envelope min with adaptive window (exact), in place,
// plus per-(mask,batch) max via atomicMax on float bits (all values >= 0).
__global__ void k_horiz() {
    __shared__ float s[WW];
    __shared__ float smax[16];
    int row = blockIdx.x;                 // m*(BB*HH) + b*HH + h
    int j = threadIdx.x;                  // 512 threads
    float* rowptr = g_dtsq + (size_t)row * WW;

    s[j] = rowptr[j];
    __syncthreads();

    float best = fminf(s[j], BIG2);       // matches reference best0 = BIG*BIG
    for (int r = 1; r < WW; ++r) {
        float rr = (float)(r * r);        // integer-exact in fp32
        if (rr >= best) break;            // rigorous cutoff: exactness preserved
        if (j >= r)      best = fminf(best, s[j - r] + rr);
        if (j + r < WW)  best = fminf(best, s[j + r] + rr);
    }
    rowptr[j] = best;

    // block max -> atomicMax
    float v = best;
    #pragma unroll
    for (int o = 16; o > 0; o >>= 1) v = fmaxf(v, __shfl_xor_sync(0xffffffffu, v, o));
    if ((j & 31) == 0) smax[j >> 5] = v;
    __syncthreads();
    if (j < 32) {
        float x = (j < 16) ? smax[j] : 0.0f;
        #pragma unroll
        for (int o = 8; o > 0; o >>= 1) x = fmaxf(x, __shfl_xor_sync(0xffffffffu, x, o));
        if (j == 0) {
            int mb = row >> 9;            // m*BB + b
            atomicMax(&g_maxbits[mb], __float_as_uint(x));
        }
    }
}

// Pass 3: fused loss = sum over pixels of (seg - gt)^2 * (dtsq_gt/mx_gt + dtsq_seg/mx_seg)
__global__ void k_final(const float* __restrict__ out, const int* __restrict__ tgt) {
    __shared__ float  sinv[2];
    __shared__ double ssum[8];
    int idx = blockIdx.x * blockDim.x + threadIdx.x;   // [b][h][w], 256 thr/block
    int b = idx >> 18;
    if (threadIdx.x == 0) {
        // m=0: gt dtm,  m=1: seg dtm.  max(.,1) subsumes any_fg / mx_safe.
        sinv[0] = 1.0f / fmaxf(__uint_as_float(g_maxbits[b]), 1.0f);
        sinv[1] = 1.0f / fmaxf(__uint_as_float(g_maxbits[BB + b]), 1.0f);
    }
    __syncthreads();

    int w = idx & (WW - 1);
    int h = (idx >> 9) & (HH - 1);
    float segv = out[((b * 2 + 1) * HH + h) * WW + w];
    float gtv  = (float)tgt[idx];
    float d    = segv - gtv;
    float dtm  = g_dtsq[idx] * sinv[0] + g_dtsq[NPIX + idx] * sinv[1];
    double v   = (double)(d * d * dtm);

    #pragma unroll
    for (int o = 16; o > 0; o >>= 1) v += __shfl_xor_sync(0xffffffffu, v, o);
    if ((threadIdx.x & 31) == 0) ssum[threadIdx.x >> 5] = v;
    __syncthreads();
    if (threadIdx.x < 32) {
        double x = (threadIdx.x < 8) ? ssum[threadIdx.x] : 0.0;
        #pragma unroll
        for (int o = 4; o > 0; o >>= 1) x += __shfl_xor_sync(0xffffffffu, x, o);
        if (threadIdx.x == 0) atomicAdd(&g_accum, x);
    }
}

__global__ void k_write(float* o) {
    o[0] = (float)(g_accum * (1.0 / (double)NPIX));
}

extern "C" void kernel_launch(void* const* d_in, const int* in_sizes, int n_in,
                              void* d_out, int out_size) {
    const float* out = (const float*)d_in[0];   // [8,2,512,512] float32
    const int*   tgt = (const int*)d_in[1];     // [8,1,512,512] int32

    k_init<<<1, 32>>>();
    k_vert<<<(NMASK * NPIX) / 256, 256>>>(out, tgt);
    k_horiz<<<NMASK * BB * HH, WW>>>();
    k_final<<<NPIX / 256, 256>>>(out, tgt);
    k_write<<<1, 1>>>((float*)d_out);
}